// round 1
// baseline (speedup 1.0000x reference)
#include <cuda_runtime.h>
#include <cuda_bf16.h>
#include <math.h>

// ---------------------------------------------------------------------------
// GWNet2: B=64, N=1024, L=13, RC=DC=32, SC=256, EC=512, OUT=12, LAYERS=8
// Internal layout for h/m/x: [B][L][C][N] (N innermost, contiguous rows of 1024)
// skip / e1 layout: [C][B*N]
// ---------------------------------------------------------------------------

#define NB 64
#define NN 1024
#define NC 32
#define NSC 256
#define NEC 512
#define NOUT 12

// device scratch (allocation-free rule: __device__ globals)
__device__ float g_hA[64 * 13 * 32 * 1024];   // 27,262,976
__device__ float g_hB[64 * 12 * 32 * 1024];   // 25,165,824
__device__ float g_m [64 * 12 * 32 * 1024];   // 25,165,824
__device__ float g_x12[64 * 12 * 32 * 2048];  // 50,331,648  (x1 | x2 per row)
__device__ float g_Bm[1024 * 2048];           // [ADP | ADP^2], row-major, ld=2048
__device__ float g_skip[256 * 64 * 1024];     // [C=256][B*N]
__device__ float g_e1 [512 * 64 * 1024];      // [C=512][B*N]

// ---------------------------------------------------------------------------
// adp = softmax(relu(nv1 @ nv2), axis=1); one block per row v
// ---------------------------------------------------------------------------
__global__ __launch_bounds__(256) void k_adp(const float* __restrict__ nv1,
                                             const float* __restrict__ nv2,
                                             float* __restrict__ Bm) {
    __shared__ float red[256];
    int v = blockIdx.x, tid = threadIdx.x;
    float n1[10];
#pragma unroll
    for (int k = 0; k < 10; k++) n1[k] = nv1[v * 10 + k];
    float a[4];
#pragma unroll
    for (int j = 0; j < 4; j++) {
        int w = tid + j * 256;
        float s = 0.f;
#pragma unroll
        for (int k = 0; k < 10; k++) s += n1[k] * nv2[k * 1024 + w];
        a[j] = fmaxf(s, 0.f);
    }
    float mx = fmaxf(fmaxf(a[0], a[1]), fmaxf(a[2], a[3]));
    red[tid] = mx; __syncthreads();
    for (int s = 128; s > 0; s >>= 1) {
        if (tid < s) red[tid] = fmaxf(red[tid], red[tid + s]);
        __syncthreads();
    }
    mx = red[0]; __syncthreads();
    float e[4]; float sum = 0.f;
#pragma unroll
    for (int j = 0; j < 4; j++) { e[j] = expf(a[j] - mx); sum += e[j]; }
    red[tid] = sum; __syncthreads();
    for (int s = 128; s > 0; s >>= 1) {
        if (tid < s) red[tid] += red[tid + s];
        __syncthreads();
    }
    float inv = 1.f / red[0];
#pragma unroll
    for (int j = 0; j < 4; j++) Bm[(long)v * 2048 + tid + j * 256] = e[j] * inv;
}

// ---------------------------------------------------------------------------
// start conv: h[b][l][c][n] = sw[c][0]*x[b,0,n,l] + sw[c][1]*x[b,1,n,l] + sb[c]
// grid: (64*13, 4), 256 thr
// ---------------------------------------------------------------------------
__global__ __launch_bounds__(256) void k_start(const float* __restrict__ x,
                                               const float* __restrict__ sw,
                                               const float* __restrict__ sb,
                                               float* __restrict__ h) {
    int bl = blockIdx.x;
    int b = bl / 13, l = bl - b * 13;
    int n = blockIdx.y * 256 + threadIdx.x;
    float x0 = x[(((long)b * 2 + 0) * 1024 + n) * 13 + l];
    float x1 = x[(((long)b * 2 + 1) * 1024 + n) * 13 + l];
    float* hb = h + ((long)(b * 13 + l) * 32) * 1024 + n;
#pragma unroll
    for (int c = 0; c < 32; c++)
        hb[(long)c * 1024] = sw[c * 2] * x0 + sw[c * 2 + 1] * x1 + sb[c];
}

// ---------------------------------------------------------------------------
// dilated conv + tanh*sigmoid gate
// m[b][l][co][n] = tanh(fw0@h[l] + fw1@h[l+d] + fb) * sig(gw0@h[l] + gw1@h[l+d] + gb)
// grid: (64*L1, 16), 256 thr; block handles (b,l, 64 n's), 4 co-groups of 8
// ---------------------------------------------------------------------------
__global__ __launch_bounds__(256) void k_dconv(const float* __restrict__ h,
                                               const float* __restrict__ fw,
                                               const float* __restrict__ fb,
                                               const float* __restrict__ gw,
                                               const float* __restrict__ gb,
                                               float* __restrict__ m,
                                               int L0, int L1, int d) {
    __shared__ float s_in[2][32][64];
    __shared__ float4 s_w[32][32];
    __shared__ float s_fb[32], s_gb[32];
    int bl = blockIdx.x;
    int b = bl / L1, l = bl - b * L1;
    int n0 = blockIdx.y * 64;
    int tid = threadIdx.x;
    for (int idx = tid; idx < 1024; idx += 256) {
        int co = idx >> 5, ci = idx & 31;
        int o = (co * 32 + ci) * 2;
        s_w[co][ci] = make_float4(fw[o], fw[o + 1], gw[o], gw[o + 1]);
    }
    if (tid < 32) { s_fb[tid] = fb[tid]; s_gb[tid] = gb[tid]; }
    const float* hb = h + ((long)(b * L0 + l) * 32) * 1024 + n0;
    for (int idx = tid; idx < 4096; idx += 256) {
        int tap = idx >> 11, ci = (idx >> 6) & 31, nl = idx & 63;
        s_in[tap][ci][nl] = hb[((long)(tap * d) * 32 + ci) * 1024 + nl];
    }
    __syncthreads();
    int nl = tid & 63, cg = tid >> 6;
    float* mo = m + ((long)(b * L1 + l) * 32) * 1024 + n0 + nl;
#pragma unroll
    for (int u = 0; u < 8; u++) {
        int co = cg * 8 + u;
        float fa = s_fb[co], ga = s_gb[co];
#pragma unroll
        for (int ci = 0; ci < 32; ci++) {
            float v0 = s_in[0][ci][nl], v1 = s_in[1][ci][nl];
            float4 w = s_w[co][ci];
            fa += w.x * v0 + w.y * v1;
            ga += w.z * v0 + w.w * v1;
        }
        mo[(long)co * 1024] = tanhf(fa) * (1.f / (1.f + expf(-ga)));
    }
}

// ---------------------------------------------------------------------------
// skip accumulation (last timestep only):
// skip[co][b*1024+n] (+)= sum_ci sw[co][ci]*m[b][L1-1][ci][n] + sb[co]
// grid: (64, 8), 256 thr (thread == co)
// ---------------------------------------------------------------------------
__global__ __launch_bounds__(256) void k_skip(const float* __restrict__ m,
                                              const float* __restrict__ sw,
                                              const float* __restrict__ sb,
                                              float* __restrict__ skip,
                                              int L1, int first) {
    __shared__ float s_m[32][128];
    int b = blockIdx.x;
    int n0 = blockIdx.y * 128;
    int tid = threadIdx.x;
    const float* mb = m + ((long)(b * L1 + (L1 - 1)) * 32) * 1024 + n0;
    for (int idx = tid; idx < 4096; idx += 256) {
        int ci = idx >> 7, nl = idx & 127;
        s_m[ci][nl] = mb[(long)ci * 1024 + nl];
    }
    __syncthreads();
    float w[32];
#pragma unroll
    for (int ci = 0; ci < 32; ci++) w[ci] = sw[tid * 32 + ci];
    float bias = sb[tid];
    float* so = skip + (long)tid * 65536 + b * 1024 + n0;
    for (int n = 0; n < 128; n += 4) {
        float a0 = bias, a1 = bias, a2 = bias, a3 = bias;
#pragma unroll
        for (int ci = 0; ci < 32; ci++) {
            float4 v = *(const float4*)&s_m[ci][n];
            a0 += w[ci] * v.x; a1 += w[ci] * v.y;
            a2 += w[ci] * v.z; a3 += w[ci] * v.w;
        }
        if (first) {
            so[n] = a0; so[n + 1] = a1; so[n + 2] = a2; so[n + 3] = a3;
        } else {
            so[n] += a0; so[n + 1] += a1; so[n + 2] += a2; so[n + 3] += a3;
        }
    }
}

// ---------------------------------------------------------------------------
// generic fp32 SGEMM: C[M,N] = A[M,K] @ B[K,N], row-major, strided.
// BM=BN=128, BK=16, 256 threads, 8x8 microtile. M,N mult of 128; K mult of 16.
// flags bit0: relu applied to B elements on load
// flags bit1: C = relu(acc + bias[row])
// ---------------------------------------------------------------------------
__global__ __launch_bounds__(256) void k_sgemm(const float* __restrict__ A,
                                               const float* __restrict__ B,
                                               float* __restrict__ C,
                                               int M, int N, int K,
                                               int lda, int ldb, int ldc,
                                               const float* __restrict__ bias,
                                               int flags) {
    __shared__ float As[16][132];
    __shared__ float Bs[16][128];
    int tid = threadIdx.x;
    int m0 = blockIdx.y * 128, n0 = blockIdx.x * 128;
    int ty = tid >> 4, tx = tid & 15;

    float acc[8][8];
#pragma unroll
    for (int i = 0; i < 8; i++)
#pragma unroll
        for (int j = 0; j < 8; j++) acc[i][j] = 0.f;

    for (int k0 = 0; k0 < K; k0 += 16) {
#pragma unroll
        for (int i = 0; i < 2; i++) {
            int f = tid + i * 256;
            int r = f >> 2, kc = (f & 3) * 4;
            float4 v = *(const float4*)(A + (long)(m0 + r) * lda + k0 + kc);
            As[kc + 0][r] = v.x; As[kc + 1][r] = v.y;
            As[kc + 2][r] = v.z; As[kc + 3][r] = v.w;
        }
#pragma unroll
        for (int i = 0; i < 2; i++) {
            int f = tid + i * 256;
            int r = f >> 5, nc = (f & 31) * 4;
            float4 v = *(const float4*)(B + (long)(k0 + r) * ldb + n0 + nc);
            if (flags & 1) {
                v.x = fmaxf(v.x, 0.f); v.y = fmaxf(v.y, 0.f);
                v.z = fmaxf(v.z, 0.f); v.w = fmaxf(v.w, 0.f);
            }
            *(float4*)&Bs[r][nc] = v;
        }
        __syncthreads();
#pragma unroll
        for (int k = 0; k < 16; k++) {
            float a[8], b[8];
            float4 a0 = *(const float4*)&As[k][ty * 8];
            float4 a1 = *(const float4*)&As[k][ty * 8 + 4];
            a[0] = a0.x; a[1] = a0.y; a[2] = a0.z; a[3] = a0.w;
            a[4] = a1.x; a[5] = a1.y; a[6] = a1.z; a[7] = a1.w;
            float4 b0 = *(const float4*)&Bs[k][tx * 8];
            float4 b1 = *(const float4*)&Bs[k][tx * 8 + 4];
            b[0] = b0.x; b[1] = b0.y; b[2] = b0.z; b[3] = b0.w;
            b[4] = b1.x; b[5] = b1.y; b[6] = b1.z; b[7] = b1.w;
#pragma unroll
            for (int i = 0; i < 8; i++)
#pragma unroll
                for (int j = 0; j < 8; j++) acc[i][j] += a[i] * b[j];
        }
        __syncthreads();
    }

#pragma unroll
    for (int i = 0; i < 8; i++) {
        int mrow = m0 + ty * 8 + i;
        float bi = (flags & 2) ? bias[mrow] : 0.f;
        float4 o0, o1;
        if (flags & 2) {
            o0.x = fmaxf(acc[i][0] + bi, 0.f); o0.y = fmaxf(acc[i][1] + bi, 0.f);
            o0.z = fmaxf(acc[i][2] + bi, 0.f); o0.w = fmaxf(acc[i][3] + bi, 0.f);
            o1.x = fmaxf(acc[i][4] + bi, 0.f); o1.y = fmaxf(acc[i][5] + bi, 0.f);
            o1.z = fmaxf(acc[i][6] + bi, 0.f); o1.w = fmaxf(acc[i][7] + bi, 0.f);
        } else {
            o0.x = acc[i][0]; o0.y = acc[i][1]; o0.z = acc[i][2]; o0.w = acc[i][3];
            o1.x = acc[i][4]; o1.y = acc[i][5]; o1.z = acc[i][6]; o1.w = acc[i][7];
        }
        *(float4*)(C + (long)mrow * ldc + n0 + tx * 8) = o0;
        *(float4*)(C + (long)mrow * ldc + n0 + tx * 8 + 4) = o1;
    }
}

// ---------------------------------------------------------------------------
// gc mix + residual + BN:
// hnew[b][l][co][n] = ((Wm@m + W1@x1 + W2@x2 + gcb) + hold[b][l+d][co][n])*scale + shift
// grid: (64*L1, 16), 256 thr
// ---------------------------------------------------------------------------
__global__ __launch_bounds__(256) void k_gc(const float* __restrict__ m,
                                            const float* __restrict__ x12,
                                            const float* __restrict__ hold,
                                            const float* __restrict__ gcw,
                                            const float* __restrict__ gcb,
                                            const float* __restrict__ bng,
                                            const float* __restrict__ bnb,
                                            float* __restrict__ hnew,
                                            int L0, int L1, int d) {
    __shared__ float s_in[3][32][64];
    __shared__ float4 s_w[32][32];
    __shared__ float s_b[32], s_sc[32], s_sh[32];
    int bl = blockIdx.x;
    int b = bl / L1, l = bl - b * L1;
    int n0 = blockIdx.y * 64;
    int tid = threadIdx.x;
    for (int idx = tid; idx < 1024; idx += 256) {
        int co = idx >> 5, ci = idx & 31;
        s_w[co][ci] = make_float4(gcw[co * 96 + ci], gcw[co * 96 + 32 + ci],
                                  gcw[co * 96 + 64 + ci], 0.f);
    }
    if (tid < 32) {
        s_b[tid] = gcb[tid];
        s_sc[tid] = bng[tid] * rsqrtf(1.f + 1e-5f);
        s_sh[tid] = bnb[tid];
    }
    const float* mb = m + ((long)(b * L1 + l) * 32) * 1024 + n0;
    const float* xb = x12 + ((long)(b * L1 + l) * 32) * 2048 + n0;
    for (int idx = tid; idx < 2048; idx += 256) {
        int ci = idx >> 6, nl = idx & 63;
        s_in[0][ci][nl] = mb[(long)ci * 1024 + nl];
        s_in[1][ci][nl] = xb[(long)ci * 2048 + nl];
        s_in[2][ci][nl] = xb[(long)ci * 2048 + 1024 + nl];
    }
    __syncthreads();
    int nl = tid & 63, cg = tid >> 6;
    const float* rb = hold + ((long)(b * L0 + l + d) * 32) * 1024 + n0 + nl;
    float* ob = hnew + ((long)(b * L1 + l) * 32) * 1024 + n0 + nl;
#pragma unroll
    for (int u = 0; u < 8; u++) {
        int co = cg * 8 + u;
        float acc = s_b[co];
#pragma unroll
        for (int ci = 0; ci < 32; ci++) {
            float4 w = s_w[co][ci];
            acc += w.x * s_in[0][ci][nl] + w.y * s_in[1][ci][nl] + w.z * s_in[2][ci][nl];
        }
        float res = rb[(long)co * 1024];
        ob[(long)co * 1024] = (acc + res) * s_sc[co] + s_sh[co];
    }
}

// ---------------------------------------------------------------------------
// final projection: out[b][o][n] = sum_c W2[o][c]*e1[c][b*1024+n] + b2[o]
// grid: 256, 256 thr (thread == column)
// ---------------------------------------------------------------------------
__global__ __launch_bounds__(256) void k_end2(const float* __restrict__ e1,
                                              const float* __restrict__ w2,
                                              const float* __restrict__ b2,
                                              float* __restrict__ out) {
    __shared__ float s_w[12 * 512];
    int tid = threadIdx.x;
    for (int idx = tid; idx < 6144; idx += 256) s_w[idx] = w2[idx];
    __syncthreads();
    int col = blockIdx.x * 256 + tid;
    int b = col >> 10, n = col & 1023;
    float acc[12];
#pragma unroll
    for (int o = 0; o < 12; o++) acc[o] = b2[o];
    for (int c = 0; c < 512; c++) {
        float v = e1[(long)c * 65536 + col];
#pragma unroll
        for (int o = 0; o < 12; o++) acc[o] += s_w[o * 512 + c] * v;
    }
#pragma unroll
    for (int o = 0; o < 12; o++) out[((long)b * 12 + o) * 1024 + n] = acc[o];
}

// ---------------------------------------------------------------------------
extern "C" void kernel_launch(void* const* d_in, const int* in_sizes, int n_in,
                              void* d_out, int out_size) {
    const float* x        = (const float*)d_in[0];
    const float* start_w  = (const float*)d_in[1];
    const float* start_b  = (const float*)d_in[2];
    const float* nodevec1 = (const float*)d_in[3];
    const float* nodevec2 = (const float*)d_in[4];
    const float* filter_w = (const float*)d_in[5];
    const float* filter_b = (const float*)d_in[6];
    const float* gate_w   = (const float*)d_in[7];
    const float* gate_b   = (const float*)d_in[8];
    const float* skip_w   = (const float*)d_in[9];
    const float* skip_b   = (const float*)d_in[10];
    const float* gc_w     = (const float*)d_in[11];
    const float* gc_b     = (const float*)d_in[12];
    const float* bn_g     = (const float*)d_in[13];
    const float* bn_b     = (const float*)d_in[14];
    const float* end1_w   = (const float*)d_in[15];
    const float* end1_b   = (const float*)d_in[16];
    const float* end2_w   = (const float*)d_in[17];
    const float* end2_b   = (const float*)d_in[18];

    float *hA, *hB, *m, *x12, *Bm, *skip, *e1;
    cudaGetSymbolAddress((void**)&hA, g_hA);
    cudaGetSymbolAddress((void**)&hB, g_hB);
    cudaGetSymbolAddress((void**)&m, g_m);
    cudaGetSymbolAddress((void**)&x12, g_x12);
    cudaGetSymbolAddress((void**)&Bm, g_Bm);
    cudaGetSymbolAddress((void**)&skip, g_skip);
    cudaGetSymbolAddress((void**)&e1, g_e1);

    // adjacency + its square into fused B matrix [ADP | ADP^2]
    k_adp<<<1024, 256>>>(nodevec1, nodevec2, Bm);
    k_sgemm<<<dim3(8, 8), 256>>>(Bm, Bm, Bm + 1024, 1024, 1024, 1024,
                                 2048, 2048, 2048, nullptr, 0);
    // start conv (transposes x into [B][L][C][N])
    k_start<<<dim3(64 * 13, 4), 256>>>(x, start_w, start_b, hA);

    const int lens[9] = {13, 12, 10, 9, 7, 6, 4, 3, 1};
    const int dil[8]  = {1, 2, 1, 2, 1, 2, 1, 2};
    float* hcur = hA;
    float* hnext = hB;

    for (int i = 0; i < 8; i++) {
        int L0 = lens[i], L1 = lens[i + 1], d = dil[i];
        k_dconv<<<dim3(64 * L1, 16), 256>>>(hcur,
                                            filter_w + i * 2048, filter_b + i * 32,
                                            gate_w + i * 2048, gate_b + i * 32,
                                            m, L0, L1, d);
        k_skip<<<dim3(64, 8), 256>>>(m, skip_w + i * 256 * 32, skip_b + i * 256,
                                     skip, L1, i == 0 ? 1 : 0);
        if (i < 7) {
            int M = 2048 * L1;
            k_sgemm<<<dim3(2048 / 128, M / 128), 256>>>(m, Bm, x12, M, 2048, 1024,
                                                        1024, 2048, 2048, nullptr, 0);
            k_gc<<<dim3(64 * L1, 16), 256>>>(m, x12, hcur,
                                             gc_w + i * 32 * 96, gc_b + i * 32,
                                             bn_g + i * 32, bn_b + i * 32,
                                             hnext, L0, L1, d);
            float* t = hcur; hcur = hnext; hnext = t;
        }
    }

    // end: e1 = relu(end1_w @ relu(skip) + b1); out = end2_w @ e1 + b2
    k_sgemm<<<dim3(65536 / 128, 512 / 128), 256>>>(end1_w, skip, e1,
                                                   512, 65536, 256,
                                                   256, 65536, 65536, end1_b, 3);
    k_end2<<<256, 256>>>(e1, end2_w, end2_b, (float*)d_out);
}